// round 1
// baseline (speedup 1.0000x reference)
#include <cuda_runtime.h>
#include <cuda_bf16.h>
#include <float.h>
#include <stdint.h>

#define BQ 8
#define NP 2048
#define KNN 20
#define MROWS (BQ*NP)        // 16384
#define EPSBN 1e-5f

// ------------------------- device scratch (global) --------------------------
__device__ float g_XT[MROWS*3];                  // x transposed to row-major (B*N,3)
__device__ float g_cat[(size_t)MROWS*512];       // x1|x2|x3|x4 channel-concat, row-major
__device__ float g_U[(size_t)MROWS*512];         // [s | t] per edge block (2O <= 512)
__device__ float g_Y[(size_t)MROWS*1024];        // stage-5 pre-BN activations
__device__ float g_D[(size_t)MROWS*NP];          // pairwise "distance" (pd) rows
__device__ float g_xx[MROWS];                    // squared norms
__device__ int   g_idx[MROWS*KNN];               // knn indices
__device__ float g_Wc[512*512];                  // stacked conv weights [W ; Wdiff]
__device__ float g_sum[1024];
__device__ float g_sumsq[1024];
__device__ float g_scale[1024];
__device__ float g_shift[1024];
__device__ float g_P[BQ*2048];                   // [maxpool(1024) | meanpool(1024)]
__device__ float g_h1[BQ*512];
__device__ float g_h2[BQ*256];

// ------------------------------- kernels ------------------------------------

__global__ void k_transpose_x(const float* __restrict__ x, float* __restrict__ XT)
{
    int i = blockIdx.x * blockDim.x + threadIdx.x;   // over 8*3*2048
    if (i >= BQ*3*NP) return;
    int b = i / (3*NP);
    int r = i % (3*NP);
    int c = r / NP;
    int n = r % NP;
    XT[((size_t)b*NP + n)*3 + c] = x[i];
}

__global__ void k_sqnorm(const float* __restrict__ X, int ldx, int xoff, int C,
                         float* __restrict__ xx)
{
    int r = blockIdx.x * blockDim.x + threadIdx.x;
    if (r >= MROWS) return;
    const float* p = X + (size_t)r*ldx + xoff;
    float s = 0.f;
    for (int c = 0; c < C; ++c) { float v = p[c]; s += v*v; }
    xx[r] = s;
}

// pd[b,n,m] = 2*dot(x_n,x_m) - xx_n - xx_m   (64x64 tile, 256 thr, 4x4/thr)
__global__ void k_dist(const float* __restrict__ X, int ldx, int xoff,
                       const float* __restrict__ xx, float* __restrict__ D, int Kd)
{
    __shared__ float As[16][68];
    __shared__ float Bs[16][68];
    int b  = blockIdx.z;
    int n0 = blockIdx.y * 64;
    int m0 = blockIdx.x * 64;
    int tid = threadIdx.x;
    int tx = tid & 15, ty = tid >> 4;
    size_t base = (size_t)b * NP;
    float acc[4][4] = {};
    for (int k0 = 0; k0 < Kd; k0 += 16) {
        for (int i = tid; i < 64*16; i += 256) {
            int r = i >> 4, kk = i & 15;
            float va = 0.f, vb = 0.f;
            if (k0 + kk < Kd) {
                va = X[(base + n0 + r)*(size_t)ldx + xoff + k0 + kk];
                vb = X[(base + m0 + r)*(size_t)ldx + xoff + k0 + kk];
            }
            As[kk][r] = va;
            Bs[kk][r] = vb;
        }
        __syncthreads();
#pragma unroll
        for (int kk = 0; kk < 16; ++kk) {
            float a[4], bb[4];
#pragma unroll
            for (int i = 0; i < 4; ++i) a[i]  = As[kk][ty*4 + i];
#pragma unroll
            for (int j = 0; j < 4; ++j) bb[j] = Bs[kk][tx*4 + j];
#pragma unroll
            for (int i = 0; i < 4; ++i)
#pragma unroll
                for (int j = 0; j < 4; ++j) acc[i][j] += a[i]*bb[j];
        }
        __syncthreads();
    }
#pragma unroll
    for (int i = 0; i < 4; ++i) {
        int n = n0 + ty*4 + i;
        float xn = xx[base + n];
#pragma unroll
        for (int j = 0; j < 4; ++j) {
            int m = m0 + tx*4 + j;
            D[(base + n)*(size_t)NP + m] = 2.f*acc[i][j] - xn - xx[base + m];
        }
    }
}

// top-20 per row; 1 warp/row, per-lane top-20 lists, stable warp argmax merge
__global__ void k_topk(const float* __restrict__ D, int* __restrict__ idxout)
{
    __shared__ float sv[8][32][20];
    __shared__ int   si[8][32][20];
    int warp = threadIdx.x >> 5, lane = threadIdx.x & 31;
    int row  = blockIdx.x * 8 + warp;
    const float* drow = D + (size_t)row * NP;

    float lv[20]; int li[20];
#pragma unroll
    for (int j = 0; j < 20; ++j) { lv[j] = -FLT_MAX; li[j] = 1 << 30; }

    for (int m = lane; m < NP; m += 32) {
        float v = drow[m];
        if (v > lv[19]) {
            float cv = v; int ci = m;
#pragma unroll
            for (int j = 0; j < 20; ++j) {
                if (cv > lv[j]) {
                    float tv = lv[j]; int ti = li[j];
                    lv[j] = cv; li[j] = ci;
                    cv = tv; ci = ti;
                }
            }
        }
    }
#pragma unroll
    for (int j = 0; j < 20; ++j) { sv[warp][lane][j] = lv[j]; si[warp][lane][j] = li[j]; }
    __syncwarp();

    int p = 0;
    float v = sv[warp][lane][0];
    int   i = si[warp][lane][0];
    for (int r = 0; r < 20; ++r) {
        float bv = v; int bi = i;
#pragma unroll
        for (int s = 16; s > 0; s >>= 1) {
            float ov = __shfl_xor_sync(0xffffffff, bv, s);
            int   oi = __shfl_xor_sync(0xffffffff, bi, s);
            if (ov > bv || (ov == bv && oi < bi)) { bv = ov; bi = oi; }
        }
        if (v == bv && i == bi) {   // unique winner (indices distinct)
            idxout[row*KNN + r] = bi;
            ++p;
            if (p < 20) { v = sv[warp][lane][p]; i = si[warp][lane][p]; }
            else        { v = -FLT_MAX; i = 1 << 30; }
        }
    }
}

// Wc[o][c] = W[o][c];  Wc[O+o][c] = W[o][C+c] - W[o][c]
__global__ void k_prepw(const float* __restrict__ W, float* __restrict__ Wc, int O, int C)
{
    int i = blockIdx.x * blockDim.x + threadIdx.x;
    if (i >= O*C) return;
    int o = i / C, c = i % C;
    float w1 = W[o*2*C + c];
    float w2 = W[o*2*C + C + c];
    Wc[o*C + c]       = w1;
    Wc[(O + o)*C + c] = w2 - w1;
}

// C = A(MxK, lda, +aoff) * B(NxK row-major)^T -> Cout(MxN, ldc, +coff)
// 64x64 tile, BK=16, 256 threads, 4x4 per thread. M,N multiples of 64.
__global__ void k_gemm(const float* __restrict__ A, int lda, int aoff,
                       const float* __restrict__ Bw, int ldb,
                       float* __restrict__ Cm, int ldc, int coff,
                       int Kd)
{
    __shared__ float As[16][68];
    __shared__ float Bs[16][68];
    int n0 = blockIdx.x * 64;
    int m0 = blockIdx.y * 64;
    int tid = threadIdx.x;
    int tx = tid & 15, ty = tid >> 4;
    float acc[4][4] = {};
    for (int k0 = 0; k0 < Kd; k0 += 16) {
        for (int i = tid; i < 64*16; i += 256) {
            int r = i >> 4, kk = i & 15;
            float va = 0.f, vb = 0.f;
            if (k0 + kk < Kd) {
                va = A [(size_t)(m0 + r)*lda + aoff + k0 + kk];
                vb = Bw[(size_t)(n0 + r)*ldb + k0 + kk];
            }
            As[kk][r] = va;
            Bs[kk][r] = vb;
        }
        __syncthreads();
#pragma unroll
        for (int kk = 0; kk < 16; ++kk) {
            float a[4], bb[4];
#pragma unroll
            for (int i = 0; i < 4; ++i) a[i]  = As[kk][ty*4 + i];
#pragma unroll
            for (int j = 0; j < 4; ++j) bb[j] = Bs[kk][tx*4 + j];
#pragma unroll
            for (int i = 0; i < 4; ++i)
#pragma unroll
                for (int j = 0; j < 4; ++j) acc[i][j] += a[i]*bb[j];
        }
        __syncthreads();
    }
#pragma unroll
    for (int i = 0; i < 4; ++i)
#pragma unroll
        for (int j = 0; j < 4; ++j)
            Cm[(size_t)(m0 + ty*4 + i)*ldc + coff + n0 + tx*4 + j] = acc[i][j];
}

__global__ void k_zero2(float* a, float* b, int n)
{
    int i = blockIdx.x * blockDim.x + threadIdx.x;
    if (i < n) { a[i] = 0.f; b[i] = 0.f; }
}

// edge stats: sum/sumsq over (b,n,k) of h = s[b,idx,o] + t[b,n,o]
__global__ void k_edge_stats(const float* __restrict__ U, int O,
                             const int* __restrict__ idx,
                             float* __restrict__ gsum, float* __restrict__ gsq)
{
    const int ld = 2*O;
    int nsub = 256 / O;
    int o   = threadIdx.x % O;
    int sub = threadIdx.x / O;
    int row0 = blockIdx.x * 16;
    float s0 = 0.f, s1 = 0.f;
    for (int r = row0 + sub; r < row0 + 16; r += nsub) {
        int b = r >> 11;
        float tc = U[(size_t)r*ld + O + o];
        const int* ir = idx + r*KNN;
#pragma unroll
        for (int k = 0; k < KNN; ++k) {
            int nb = ir[k];
            float h = U[((size_t)(b << 11) + nb)*ld + o] + tc;
            s0 += h; s1 += h*h;
        }
    }
    atomicAdd(&gsum[o], s0);
    atomicAdd(&gsq[o],  s1);
}

__global__ void k_bn_finalize(const float* __restrict__ gsum, const float* __restrict__ gsq,
                              const float* __restrict__ g, const float* __restrict__ bch,
                              float* __restrict__ scale, float* __restrict__ shift,
                              int O, float invcnt)
{
    int o = blockIdx.x * blockDim.x + threadIdx.x;
    if (o >= O) return;
    float m  = gsum[o] * invcnt;
    float vv = gsq[o] * invcnt - m*m;
    float sc = g[o] / sqrtf(vv + EPSBN);
    scale[o] = sc;
    shift[o] = bch[o] - m*sc;
}

// edge output: cat[row, catoff+o] = max_k lrelu(scale*h + shift)
__global__ void k_edge_out(const float* __restrict__ U, int O,
                           const int* __restrict__ idx,
                           const float* __restrict__ scale, const float* __restrict__ shift,
                           float* __restrict__ cat, int catoff)
{
    const int ld = 2*O;
    int nsub = 256 / O;
    int o   = threadIdx.x % O;
    int sub = threadIdx.x / O;
    int row0 = blockIdx.x * 16;
    float sc = scale[o], sh = shift[o];
    for (int r = row0 + sub; r < row0 + 16; r += nsub) {
        int b = r >> 11;
        float tc = U[(size_t)r*ld + O + o];
        const int* ir = idx + r*KNN;
        float mx = -FLT_MAX;
#pragma unroll
        for (int k = 0; k < KNN; ++k) {
            float h = U[((size_t)(b << 11) + ir[k])*ld + o] + tc;
            h = h*sc + sh;
            h = (h >= 0.f) ? h : 0.2f*h;
            mx = fmaxf(mx, h);
        }
        cat[(size_t)r*512 + catoff + o] = mx;
    }
}

// stage-5 plain stats over 16384 rows x 1024 cols
__global__ void k_plain_stats(const float* __restrict__ Y,
                              float* __restrict__ gsum, float* __restrict__ gsq)
{
    int o  = blockIdx.y * 256 + threadIdx.x;
    int r0 = blockIdx.x * 256;
    float s0 = 0.f, s1 = 0.f;
    for (int r = r0; r < r0 + 256; ++r) {
        float v = Y[(size_t)r*1024 + o];
        s0 += v; s1 += v*v;
    }
    atomicAdd(&gsum[o], s0);
    atomicAdd(&gsq[o],  s1);
}

// BN+lrelu then max/mean pool over n (per batch, per channel)
__global__ void k_pool(const float* __restrict__ Y,
                       const float* __restrict__ scale, const float* __restrict__ shift,
                       float* __restrict__ P)
{
    int b = blockIdx.x;
    int o = blockIdx.y * 256 + threadIdx.x;
    float sc = scale[o], sh = shift[o];
    float mx = -FLT_MAX, sm = 0.f;
    for (int n = 0; n < NP; ++n) {
        float v = Y[((size_t)b*NP + n)*1024 + o]*sc + sh;
        v = (v >= 0.f) ? v : 0.2f*v;
        mx = fmaxf(mx, v);
        sm += v;
    }
    P[b*2048 + o]        = mx;
    P[b*2048 + 1024 + o] = sm * (1.f/(float)NP);
}

// Out[b,f] = dot(In[b,:Kd], W[f,:Kd]) + bias[f]
__global__ void k_fc(const float* __restrict__ In, const float* __restrict__ W,
                     const float* __restrict__ bias, float* __restrict__ Out,
                     int F, int Kd)
{
    int f = blockIdx.x * blockDim.x + threadIdx.x;
    if (f >= F) return;
    float acc[BQ] = {};
    const float* wr = W + (size_t)f*Kd;
    for (int j = 0; j < Kd; ++j) {
        float w = wr[j];
#pragma unroll
        for (int b = 0; b < BQ; ++b) acc[b] += In[b*Kd + j]*w;
    }
    float bb = bias ? bias[f] : 0.f;
#pragma unroll
    for (int b = 0; b < BQ; ++b) Out[b*F + f] = acc[b] + bb;
}

// BN over the 8-sample batch axis + lrelu, in place
__global__ void k_bn_batch(float* __restrict__ X, const float* __restrict__ g,
                           const float* __restrict__ bch, int F)
{
    int f = blockIdx.x * blockDim.x + threadIdx.x;
    if (f >= F) return;
    float m = 0.f;
#pragma unroll
    for (int b = 0; b < BQ; ++b) m += X[b*F + f];
    m *= (1.f/BQ);
    float vv = 0.f;
#pragma unroll
    for (int b = 0; b < BQ; ++b) { float d = X[b*F + f] - m; vv += d*d; }
    vv *= (1.f/BQ);
    float sc = g[f] / sqrtf(vv + EPSBN);
    float sh = bch[f] - m*sc;
#pragma unroll
    for (int b = 0; b < BQ; ++b) {
        float z = X[b*F + f]*sc + sh;
        X[b*F + f] = (z >= 0.f) ? z : 0.2f*z;
    }
}

// ------------------------------- host side ----------------------------------

struct Ptrs {
    float *XT, *CAT, *U, *Y, *D, *XX, *WC, *SUM, *SQ, *SC, *SH, *P, *H1, *H2;
    int *IDX;
};

static void run_edge_block(const Ptrs& p,
                           const float* Xact, int ldx, int xoff, int C, int O,
                           const float* W, const float* g, const float* bch,
                           int catoff, bool do_knn)
{
    if (do_knn) {
        k_sqnorm<<<MROWS/256, 256>>>(Xact, ldx, xoff, C, p.XX);
        k_dist<<<dim3(NP/64, NP/64, BQ), 256>>>(Xact, ldx, xoff, p.XX, p.D, C);
        k_topk<<<MROWS/8, 256>>>(p.D, p.IDX);
    }
    k_prepw<<<(O*C + 255)/256, 256>>>(W, p.WC, O, C);
    k_gemm<<<dim3((2*O)/64, MROWS/64), 256>>>(Xact, ldx, xoff, p.WC, C, p.U, 2*O, 0, C);
    k_zero2<<<(O + 255)/256, 256>>>(p.SUM, p.SQ, O);
    k_edge_stats<<<MROWS/16, 256>>>(p.U, O, p.IDX, p.SUM, p.SQ);
    k_bn_finalize<<<(O + 255)/256, 256>>>(p.SUM, p.SQ, g, bch, p.SC, p.SH, O,
                                          1.f/((float)MROWS*(float)KNN));
    k_edge_out<<<MROWS/16, 256>>>(p.U, O, p.IDX, p.SC, p.SH, p.CAT, catoff);
}

extern "C" void kernel_launch(void* const* d_in, const int* in_sizes, int n_in,
                              void* d_out, int out_size)
{
    const float* x   = (const float*)d_in[0];
    const float* W1  = (const float*)d_in[1];
    const float* g1  = (const float*)d_in[2];
    const float* b1  = (const float*)d_in[3];
    const float* W2  = (const float*)d_in[4];
    const float* g2  = (const float*)d_in[5];
    const float* b2  = (const float*)d_in[6];
    const float* W3  = (const float*)d_in[7];
    const float* g3  = (const float*)d_in[8];
    const float* b3  = (const float*)d_in[9];
    const float* W4  = (const float*)d_in[10];
    const float* g4  = (const float*)d_in[11];
    const float* b4  = (const float*)d_in[12];
    const float* W5  = (const float*)d_in[13];
    const float* g5  = (const float*)d_in[14];
    const float* b5  = (const float*)d_in[15];
    const float* Wl1 = (const float*)d_in[16];
    const float* g6  = (const float*)d_in[17];
    const float* b6  = (const float*)d_in[18];
    const float* Wl2 = (const float*)d_in[19];
    const float* bl2 = (const float*)d_in[20];
    const float* g7  = (const float*)d_in[21];
    const float* b7  = (const float*)d_in[22];
    const float* Wl3 = (const float*)d_in[23];
    const float* bl3 = (const float*)d_in[24];
    (void)in_sizes; (void)n_in;

    Ptrs p;
    cudaGetSymbolAddress((void**)&p.XT,  g_XT);
    cudaGetSymbolAddress((void**)&p.CAT, g_cat);
    cudaGetSymbolAddress((void**)&p.U,   g_U);
    cudaGetSymbolAddress((void**)&p.Y,   g_Y);
    cudaGetSymbolAddress((void**)&p.D,   g_D);
    cudaGetSymbolAddress((void**)&p.XX,  g_xx);
    cudaGetSymbolAddress((void**)&p.WC,  g_Wc);
    cudaGetSymbolAddress((void**)&p.SUM, g_sum);
    cudaGetSymbolAddress((void**)&p.SQ,  g_sumsq);
    cudaGetSymbolAddress((void**)&p.SC,  g_scale);
    cudaGetSymbolAddress((void**)&p.SH,  g_shift);
    cudaGetSymbolAddress((void**)&p.P,   g_P);
    cudaGetSymbolAddress((void**)&p.H1,  g_h1);
    cudaGetSymbolAddress((void**)&p.H2,  g_h2);
    cudaGetSymbolAddress((void**)&p.IDX, g_idx);

    // x (8,3,2048) -> row-major (B*N, 3)
    k_transpose_x<<<(BQ*3*NP + 255)/256, 256>>>(x, p.XT);

    // edge block 1: knn on raw x (C=3), conv W1 (64 x 6) -> cat[:, 0:64]
    run_edge_block(p, p.XT, 3, 0, 3, 64, W1, g1, b1, 0, true);
    // edge block 2: knn on x1 (C=64), W2 (64 x 128) -> cat[:, 64:128]
    run_edge_block(p, p.CAT, 512, 0, 64, 64, W2, g2, b2, 64, true);
    // edge block 3: knn on x2 (C=64), W3 (128 x 128) -> cat[:, 128:256]
    run_edge_block(p, p.CAT, 512, 64, 64, 128, W3, g3, b3, 128, true);
    // edge block 4: knn on x3 (C=128), W4 (256 x 256) -> cat[:, 256:512]
    run_edge_block(p, p.CAT, 512, 128, 128, 256, W4, g4, b4, 256, true);

    // stage 5: Y = cat (16384x512) @ W5^T (1024x512)
    k_gemm<<<dim3(1024/64, MROWS/64), 256>>>(p.CAT, 512, 0, W5, 512, p.Y, 1024, 0, 512);
    k_zero2<<<(1024 + 255)/256, 256>>>(p.SUM, p.SQ, 1024);
    k_plain_stats<<<dim3(MROWS/256, 4), 256>>>(p.Y, p.SUM, p.SQ);
    k_bn_finalize<<<4, 256>>>(p.SUM, p.SQ, g5, b5, p.SC, p.SH, 1024, 1.f/(float)MROWS);
    k_pool<<<dim3(BQ, 4), 256>>>(p.Y, p.SC, p.SH, p.P);

    // FC head
    k_fc<<<2, 256>>>(p.P,  Wl1, nullptr, p.H1, 512, 2048);
    k_bn_batch<<<2, 256>>>(p.H1, g6, b6, 512);
    k_fc<<<1, 256>>>(p.H1, Wl2, bl2,     p.H2, 256, 512);
    k_bn_batch<<<1, 256>>>(p.H2, g7, b7, 256);
    k_fc<<<1, 64>>>(p.H2, Wl3, bl3, (float*)d_out, 40, 256);
}

// round 2
// speedup vs baseline: 1.2046x; 1.2046x over previous
#include <cuda_runtime.h>
#include <cuda_bf16.h>
#include <float.h>
#include <stdint.h>

#define BQ 8
#define NP 2048
#define KNN 20
#define MROWS (BQ*NP)        // 16384
#define EPSBN 1e-5f

// ------------------------- device scratch (global) --------------------------
__device__ float g_XT[MROWS*3];
__device__ float g_cat[(size_t)MROWS*512];
__device__ float g_U[(size_t)MROWS*512];
__device__ float g_Y[(size_t)MROWS*1024];        // stage-5 activations / edge hmax-hmin scratch
__device__ float g_D[(size_t)MROWS*NP];
__device__ float g_xx[MROWS];
__device__ int   g_idx[MROWS*KNN];
__device__ float g_Wc[512*512];
__device__ float g_sum[1024];
__device__ float g_sumsq[1024];
__device__ float g_scale[1024];
__device__ float g_shift[1024];
__device__ float g_P[BQ*2048];
__device__ float g_h1[BQ*512];
__device__ float g_h2[BQ*256];
__device__ unsigned int g_pmax[BQ*1024];
__device__ float g_psum[BQ*1024];

// ------------------------------ helpers -------------------------------------

__device__ __forceinline__ unsigned int fenc(float v) {
    unsigned int b = __float_as_uint(v);
    return (b & 0x80000000u) ? ~b : (b | 0x80000000u);
}
__device__ __forceinline__ float fdec(unsigned int u) {
    unsigned int b = (u & 0x80000000u) ? (u ^ 0x80000000u) : ~u;
    return __uint_as_float(b);
}

// ------------------------------- kernels ------------------------------------

__global__ void k_transpose_x(const float* __restrict__ x, float* __restrict__ XT)
{
    int i = blockIdx.x * blockDim.x + threadIdx.x;
    if (i >= BQ*3*NP) return;
    int b = i / (3*NP);
    int r = i % (3*NP);
    int c = r / NP;
    int n = r % NP;
    XT[((size_t)b*NP + n)*3 + c] = x[i];
}

__global__ void k_sqnorm(const float* __restrict__ X, int ldx, int xoff, int C,
                         float* __restrict__ xx)
{
    int r = blockIdx.x * blockDim.x + threadIdx.x;
    if (r >= MROWS) return;
    const float* p = X + (size_t)r*ldx + xoff;
    float s = 0.f;
    for (int c = 0; c < C; ++c) { float v = p[c]; s += v*v; }
    xx[r] = s;
}

// ---- small 64x64 GEMM variants (used only for K=3 cases, edge block 1) ----

__global__ void k_dist64(const float* __restrict__ X, int ldx, int xoff,
                         const float* __restrict__ xx, float* __restrict__ D, int Kd)
{
    __shared__ float As[16][68];
    __shared__ float Bs[16][68];
    int b  = blockIdx.z;
    int n0 = blockIdx.y * 64;
    int m0 = blockIdx.x * 64;
    int tid = threadIdx.x;
    int tx = tid & 15, ty = tid >> 4;
    size_t base = (size_t)b * NP;
    float acc[4][4] = {};
    for (int k0 = 0; k0 < Kd; k0 += 16) {
        for (int i = tid; i < 64*16; i += 256) {
            int r = i >> 4, kk = i & 15;
            float va = 0.f, vb = 0.f;
            if (k0 + kk < Kd) {
                va = X[(base + n0 + r)*(size_t)ldx + xoff + k0 + kk];
                vb = X[(base + m0 + r)*(size_t)ldx + xoff + k0 + kk];
            }
            As[kk][r] = va;
            Bs[kk][r] = vb;
        }
        __syncthreads();
#pragma unroll
        for (int kk = 0; kk < 16; ++kk) {
            float a[4], bb[4];
#pragma unroll
            for (int i = 0; i < 4; ++i) a[i]  = As[kk][ty*4 + i];
#pragma unroll
            for (int j = 0; j < 4; ++j) bb[j] = Bs[kk][tx*4 + j];
#pragma unroll
            for (int i = 0; i < 4; ++i)
#pragma unroll
                for (int j = 0; j < 4; ++j) acc[i][j] += a[i]*bb[j];
        }
        __syncthreads();
    }
#pragma unroll
    for (int i = 0; i < 4; ++i) {
        int n = n0 + ty*4 + i;
        float xn = xx[base + n];
#pragma unroll
        for (int j = 0; j < 4; ++j) {
            int m = m0 + tx*4 + j;
            D[(base + n)*(size_t)NP + m] = 2.f*acc[i][j] - xn - xx[base + m];
        }
    }
}

__global__ void k_gemm64(const float* __restrict__ A, int lda, int aoff,
                         const float* __restrict__ Bw, int ldb,
                         float* __restrict__ Cm, int ldc, int coff,
                         int Kd)
{
    __shared__ float As[16][68];
    __shared__ float Bs[16][68];
    int n0 = blockIdx.x * 64;
    int m0 = blockIdx.y * 64;
    int tid = threadIdx.x;
    int tx = tid & 15, ty = tid >> 4;
    float acc[4][4] = {};
    for (int k0 = 0; k0 < Kd; k0 += 16) {
        for (int i = tid; i < 64*16; i += 256) {
            int r = i >> 4, kk = i & 15;
            float va = 0.f, vb = 0.f;
            if (k0 + kk < Kd) {
                va = A [(size_t)(m0 + r)*lda + aoff + k0 + kk];
                vb = Bw[(size_t)(n0 + r)*ldb + k0 + kk];
            }
            As[kk][r] = va;
            Bs[kk][r] = vb;
        }
        __syncthreads();
#pragma unroll
        for (int kk = 0; kk < 16; ++kk) {
            float a[4], bb[4];
#pragma unroll
            for (int i = 0; i < 4; ++i) a[i]  = As[kk][ty*4 + i];
#pragma unroll
            for (int j = 0; j < 4; ++j) bb[j] = Bs[kk][tx*4 + j];
#pragma unroll
            for (int i = 0; i < 4; ++i)
#pragma unroll
                for (int j = 0; j < 4; ++j) acc[i][j] += a[i]*bb[j];
        }
        __syncthreads();
    }
#pragma unroll
    for (int i = 0; i < 4; ++i)
#pragma unroll
        for (int j = 0; j < 4; ++j)
            Cm[(size_t)(m0 + ty*4 + i)*ldc + coff + n0 + tx*4 + j] = acc[i][j];
}

// ---- 128x128x16 fp32 GEMM core (K must be a multiple of 16, offsets 16B aligned)

// shared tile store with XOR swizzle:
//   f in [0,512): m=f>>2, kq=f&3; element A[m0+m][k0+4kq+j] -> S[(4kq+j)*128 + (m ^ (kq<<3))]
__device__ __forceinline__ void tile_store(float* S, int f, float4 v)
{
    int m  = f >> 2;
    int kq = f & 3;
    int col = m ^ (kq << 3);
    S[(4*kq + 0)*128 + col] = v.x;
    S[(4*kq + 1)*128 + col] = v.y;
    S[(4*kq + 2)*128 + col] = v.z;
    S[(4*kq + 3)*128 + col] = v.w;
}

__global__ void __launch_bounds__(256, 2)
k_gemm128(const float* __restrict__ A, int lda, int aoff,
          const float* __restrict__ Bw, int ldb,
          float* __restrict__ Cm, int ldc, int coff,
          int Kd)
{
    __shared__ float As[16*128];
    __shared__ float Bs[16*128];
    int n0 = blockIdx.x * 128;
    int m0 = blockIdx.y * 128;
    int t  = threadIdx.x;
    int tx = t & 15, ty = t >> 4;

    float acc[8][8] = {};

    int f0 = t, f1 = t + 256;
    // prefetch k0 = 0
    float4 pa0 = *(const float4*)(A  + (size_t)(m0 + (f0>>2))*lda + aoff + (f0&3)*4);
    float4 pa1 = *(const float4*)(A  + (size_t)(m0 + (f1>>2))*lda + aoff + (f1&3)*4);
    float4 pb0 = *(const float4*)(Bw + (size_t)(n0 + (f0>>2))*ldb + (f0&3)*4);
    float4 pb1 = *(const float4*)(Bw + (size_t)(n0 + (f1>>2))*ldb + (f1&3)*4);

    for (int k0 = 0; k0 < Kd; k0 += 16) {
        tile_store(As, f0, pa0);
        tile_store(As, f1, pa1);
        tile_store(Bs, f0, pb0);
        tile_store(Bs, f1, pb1);
        __syncthreads();
        if (k0 + 16 < Kd) {
            int kn = k0 + 16;
            pa0 = *(const float4*)(A  + (size_t)(m0 + (f0>>2))*lda + aoff + kn + (f0&3)*4);
            pa1 = *(const float4*)(A  + (size_t)(m0 + (f1>>2))*lda + aoff + kn + (f1&3)*4);
            pb0 = *(const float4*)(Bw + (size_t)(n0 + (f0>>2))*ldb + kn + (f0&3)*4);
            pb1 = *(const float4*)(Bw + (size_t)(n0 + (f1>>2))*ldb + kn + (f1&3)*4);
        }
#pragma unroll
        for (int kk = 0; kk < 16; ++kk) {
            int swz = (kk >> 2) << 3;
            const float4* pa = (const float4*)&As[kk*128 + ((ty*8) ^ swz)];
            const float4* pb = (const float4*)&Bs[kk*128 + ((tx*8) ^ swz)];
            float4 a03 = pa[0], a47 = pa[1];
            float4 b03 = pb[0], b47 = pb[1];
            float a_[8] = {a03.x,a03.y,a03.z,a03.w,a47.x,a47.y,a47.z,a47.w};
            float b_[8] = {b03.x,b03.y,b03.z,b03.w,b47.x,b47.y,b47.z,b47.w};
#pragma unroll
            for (int i = 0; i < 8; ++i)
#pragma unroll
                for (int j = 0; j < 8; ++j) acc[i][j] += a_[i]*b_[j];
        }
        __syncthreads();
    }
#pragma unroll
    for (int i = 0; i < 8; ++i) {
        float* cp = Cm + (size_t)(m0 + ty*8 + i)*ldc + coff + n0 + tx*8;
        float4 v0 = {acc[i][0], acc[i][1], acc[i][2], acc[i][3]};
        float4 v1 = {acc[i][4], acc[i][5], acc[i][6], acc[i][7]};
        ((float4*)cp)[0] = v0;
        ((float4*)cp)[1] = v1;
    }
}

__global__ void __launch_bounds__(256, 2)
k_dist128(const float* __restrict__ X, int ldx, int xoff,
          const float* __restrict__ xx, float* __restrict__ D, int Kd)
{
    __shared__ float As[16*128];
    __shared__ float Bs[16*128];
    int b  = blockIdx.z;
    int m0 = blockIdx.x * 128;   // neighbor cols
    int n0 = blockIdx.y * 128;   // query rows
    size_t base = (size_t)b * NP;
    int t  = threadIdx.x;
    int tx = t & 15, ty = t >> 4;

    float acc[8][8] = {};

    int f0 = t, f1 = t + 256;
    float4 pa0 = *(const float4*)(X + (base + n0 + (f0>>2))*(size_t)ldx + xoff + (f0&3)*4);
    float4 pa1 = *(const float4*)(X + (base + n0 + (f1>>2))*(size_t)ldx + xoff + (f1&3)*4);
    float4 pb0 = *(const float4*)(X + (base + m0 + (f0>>2))*(size_t)ldx + xoff + (f0&3)*4);
    float4 pb1 = *(const float4*)(X + (base + m0 + (f1>>2))*(size_t)ldx + xoff + (f1&3)*4);

    for (int k0 = 0; k0 < Kd; k0 += 16) {
        tile_store(As, f0, pa0);
        tile_store(As, f1, pa1);
        tile_store(Bs, f0, pb0);
        tile_store(Bs, f1, pb1);
        __syncthreads();
        if (k0 + 16 < Kd) {
            int kn = k0 + 16;
            pa0 = *(const float4*)(X + (base + n0 + (f0>>2))*(size_t)ldx + xoff + kn + (f0&3)*4);
            pa1 = *(const float4*)(X + (base + n0 + (f1>>2))*(size_t)ldx + xoff + kn + (f1&3)*4);
            pb0 = *(const float4*)(X + (base + m0 + (f0>>2))*(size_t)ldx + xoff + kn + (f0&3)*4);
            pb1 = *(const float4*)(X + (base + m0 + (f1>>2))*(size_t)ldx + xoff + kn + (f1&3)*4);
        }
#pragma unroll
        for (int kk = 0; kk < 16; ++kk) {
            int swz = (kk >> 2) << 3;
            const float4* pa = (const float4*)&As[kk*128 + ((ty*8) ^ swz)];
            const float4* pb = (const float4*)&Bs[kk*128 + ((tx*8) ^ swz)];
            float4 a03 = pa[0], a47 = pa[1];
            float4 b03 = pb[0], b47 = pb[1];
            float a_[8] = {a03.x,a03.y,a03.z,a03.w,a47.x,a47.y,a47.z,a47.w};
            float b_[8] = {b03.x,b03.y,b03.z,b03.w,b47.x,b47.y,b47.z,b47.w};
#pragma unroll
            for (int i = 0; i < 8; ++i)
#pragma unroll
                for (int j = 0; j < 8; ++j) acc[i][j] += a_[i]*b_[j];
        }
        __syncthreads();
    }
    float xm[8];
#pragma unroll
    for (int j = 0; j < 8; ++j) xm[j] = xx[base + m0 + tx*8 + j];
#pragma unroll
    for (int i = 0; i < 8; ++i) {
        int n = n0 + ty*8 + i;
        float xn = xx[base + n];
        float* dp = D + (base + n)*(size_t)NP + m0 + tx*8;
        float4 v0, v1;
        v0.x = 2.f*acc[i][0] - xn - xm[0];
        v0.y = 2.f*acc[i][1] - xn - xm[1];
        v0.z = 2.f*acc[i][2] - xn - xm[2];
        v0.w = 2.f*acc[i][3] - xn - xm[3];
        v1.x = 2.f*acc[i][4] - xn - xm[4];
        v1.y = 2.f*acc[i][5] - xn - xm[5];
        v1.z = 2.f*acc[i][6] - xn - xm[6];
        v1.w = 2.f*acc[i][7] - xn - xm[7];
        ((float4*)dp)[0] = v0;
        ((float4*)dp)[1] = v1;
    }
}

// ---- top-20 per row; 1 warp/row, float4 scan, u64 packed merge ----
__global__ void k_topk(const float* __restrict__ D, int* __restrict__ idxout)
{
    __shared__ unsigned long long keys[4][32][KNN];
    int warp = threadIdx.x >> 5, lane = threadIdx.x & 31;
    int row  = blockIdx.x * 4 + warp;
    const float4* drow = (const float4*)(D + (size_t)row * NP);

    float lv[KNN]; int li[KNN];
#pragma unroll
    for (int j = 0; j < KNN; ++j) { lv[j] = -FLT_MAX; li[j] = 0; }

#pragma unroll 4
    for (int it = 0; it < 16; ++it) {
        int f = it*32 + lane;
        float4 v4 = drow[f];
        float vv[4] = {v4.x, v4.y, v4.z, v4.w};
#pragma unroll
        for (int j4 = 0; j4 < 4; ++j4) {
            float v = vv[j4];
            if (v > lv[KNN-1]) {
                float cv = v; int ci = f*4 + j4;
#pragma unroll
                for (int j = 0; j < KNN; ++j) {
                    if (cv > lv[j]) {
                        float tv = lv[j]; int ti = li[j];
                        lv[j] = cv; li[j] = ci;
                        cv = tv; ci = ti;
                    }
                }
            }
        }
    }
#pragma unroll
    for (int j = 0; j < KNN; ++j)
        keys[warp][lane][j] =
            ((unsigned long long)fenc(lv[j]) << 32) | (unsigned int)(NP - 1 - li[j]);
    __syncwarp();

    int p = 0;
    unsigned long long k = keys[warp][lane][0];
    for (int r = 0; r < KNN; ++r) {
        unsigned long long best = k;
#pragma unroll
        for (int s = 16; s > 0; s >>= 1) {
            unsigned long long o = __shfl_xor_sync(0xffffffffu, best, s);
            if (o > best) best = o;
        }
        if (lane == 0)
            idxout[row*KNN + r] = NP - 1 - (int)(best & 0xffffffffull);
        if (k == best) {
            ++p;
            k = (p < KNN) ? keys[warp][lane][p] : 0ull;
        }
    }
}

// Wc[o][c] = W[o][c];  Wc[O+o][c] = W[o][C+c] - W[o][c]
__global__ void k_prepw(const float* __restrict__ W, float* __restrict__ Wc, int O, int C)
{
    int i = blockIdx.x * blockDim.x + threadIdx.x;
    if (i >= O*C) return;
    int o = i / C, c = i % C;
    float w1 = W[o*2*C + c];
    float w2 = W[o*2*C + C + c];
    Wc[o*C + c]       = w1;
    Wc[(O + o)*C + c] = w2 - w1;
}

__global__ void k_zero2(float* a, float* b, int n)
{
    int i = blockIdx.x * blockDim.x + threadIdx.x;
    if (i < n) { a[i] = 0.f; b[i] = 0.f; }
}

// fused edge pass: one gather computes BN stats AND per-(row,o) hmax/hmin
// hmax -> HM[r*1024 + o], hmin -> HM[r*1024 + 512 + o]
__global__ void k_edge_fuse(const float* __restrict__ U, int O,
                            const int* __restrict__ idx,
                            float* __restrict__ HM,
                            float* __restrict__ gsum, float* __restrict__ gsq)
{
    const int ld = 2*O;
    int nsub = 256 / O;
    int o   = threadIdx.x % O;
    int sub = threadIdx.x / O;
    int row0 = blockIdx.x * 16;
    float s0 = 0.f, s1 = 0.f;
    for (int r = row0 + sub; r < row0 + 16; r += nsub) {
        int b = r >> 11;
        float tc = U[(size_t)r*ld + O + o];
        const int* ir = idx + r*KNN;
        float mx = -FLT_MAX, mn = FLT_MAX;
#pragma unroll
        for (int k = 0; k < KNN; ++k) {
            int nb = ir[k];
            float h = U[((size_t)(b << 11) + nb)*ld + o] + tc;
            s0 += h; s1 += h*h;
            mx = fmaxf(mx, h);
            mn = fminf(mn, h);
        }
        HM[(size_t)r*1024 + o]       = mx;
        HM[(size_t)r*1024 + 512 + o] = mn;
    }
    atomicAdd(&gsum[o], s0);
    atomicAdd(&gsq[o],  s1);
}

__global__ void k_bn_finalize(const float* __restrict__ gsum, const float* __restrict__ gsq,
                              const float* __restrict__ g, const float* __restrict__ bch,
                              float* __restrict__ scale, float* __restrict__ shift,
                              int O, float invcnt)
{
    int o = blockIdx.x * blockDim.x + threadIdx.x;
    if (o >= O) return;
    float m  = gsum[o] * invcnt;
    float vv = gsq[o] * invcnt - m*m;
    float sc = g[o] / sqrtf(vv + EPSBN);
    scale[o] = sc;
    shift[o] = bch[o] - m*sc;
}

// elementwise: cat[r, catoff+o] = lrelu(sc * (sc>=0 ? hmax : hmin) + sh)
__global__ void k_edge_apply(const float* __restrict__ HM, int O,
                             const float* __restrict__ scale, const float* __restrict__ shift,
                             float* __restrict__ cat, int catoff)
{
    int i = blockIdx.x * blockDim.x + threadIdx.x;
    if (i >= MROWS*O) return;
    int r = i / O, o = i % O;
    float sc = scale[o], sh = shift[o];
    float h = (sc >= 0.f) ? HM[(size_t)r*1024 + o] : HM[(size_t)r*1024 + 512 + o];
    float z = h*sc + sh;
    cat[(size_t)r*512 + catoff + o] = (z >= 0.f) ? z : 0.2f*z;
}

__global__ void k_plain_stats(const float* __restrict__ Y,
                              float* __restrict__ gsum, float* __restrict__ gsq)
{
    int o  = blockIdx.y * 256 + threadIdx.x;
    int r0 = blockIdx.x * 256;
    float s0 = 0.f, s1 = 0.f;
    for (int r = r0; r < r0 + 256; ++r) {
        float v = Y[(size_t)r*1024 + o];
        s0 += v; s1 += v*v;
    }
    atomicAdd(&gsum[o], s0);
    atomicAdd(&gsq[o],  s1);
}

__global__ void k_pool_init(unsigned int* pmax, float* psum)
{
    int i = blockIdx.x * blockDim.x + threadIdx.x;
    if (i < BQ*1024) { pmax[i] = 0u; psum[i] = 0.f; }
}

__global__ void k_pool_part(const float* __restrict__ Y,
                            const float* __restrict__ scale, const float* __restrict__ shift,
                            unsigned int* __restrict__ pmax, float* __restrict__ psum)
{
    int b  = blockIdx.x;
    int o  = blockIdx.y * 256 + threadIdx.x;
    int n0 = blockIdx.z * 256;
    float sc = scale[o], sh = shift[o];
    float mx = -FLT_MAX, sm = 0.f;
    for (int n = n0; n < n0 + 256; ++n) {
        float v = Y[((size_t)b*NP + n)*1024 + o]*sc + sh;
        v = (v >= 0.f) ? v : 0.2f*v;
        mx = fmaxf(mx, v);
        sm += v;
    }
    atomicMax(&pmax[b*1024 + o], fenc(mx));
    atomicAdd(&psum[b*1024 + o], sm);
}

__global__ void k_pool_fin(const unsigned int* __restrict__ pmax,
                           const float* __restrict__ psum, float* __restrict__ P)
{
    int i = blockIdx.x * blockDim.x + threadIdx.x;
    if (i >= BQ*1024) return;
    int b = i >> 10, o = i & 1023;
    P[b*2048 + o]        = fdec(pmax[i]);
    P[b*2048 + 1024 + o] = psum[i] * (1.f/(float)NP);
}

__global__ void k_fc(const float* __restrict__ In, const float* __restrict__ W,
                     const float* __restrict__ bias, float* __restrict__ Out,
                     int F, int Kd)
{
    int f = blockIdx.x * blockDim.x + threadIdx.x;
    if (f >= F) return;
    float acc[BQ] = {};
    const float* wr = W + (size_t)f*Kd;
    for (int j = 0; j < Kd; ++j) {
        float w = wr[j];
#pragma unroll
        for (int b = 0; b < BQ; ++b) acc[b] += In[b*Kd + j]*w;
    }
    float bb = bias ? bias[f] : 0.f;
#pragma unroll
    for (int b = 0; b < BQ; ++b) Out[b*F + f] = acc[b] + bb;
}

__global__ void k_bn_batch(float* __restrict__ X, const float* __restrict__ g,
                           const float* __restrict__ bch, int F)
{
    int f = blockIdx.x * blockDim.x + threadIdx.x;
    if (f >= F) return;
    float m = 0.f;
#pragma unroll
    for (int b = 0; b < BQ; ++b) m += X[b*F + f];
    m *= (1.f/BQ);
    float vv = 0.f;
#pragma unroll
    for (int b = 0; b < BQ; ++b) { float d = X[b*F + f] - m; vv += d*d; }
    vv *= (1.f/BQ);
    float sc = g[f] / sqrtf(vv + EPSBN);
    float sh = bch[f] - m*sc;
#pragma unroll
    for (int b = 0; b < BQ; ++b) {
        float z = X[b*F + f]*sc + sh;
        X[b*F + f] = (z >= 0.f) ? z : 0.2f*z;
    }
}

// ------------------------------- host side ----------------------------------

struct Ptrs {
    float *XT, *CAT, *U, *Y, *D, *XX, *WC, *SUM, *SQ, *SC, *SH, *P, *H1, *H2, *PSUM;
    unsigned int *PMAX;
    int *IDX;
};

static void run_edge_block(const Ptrs& p,
                           const float* Xact, int ldx, int xoff, int C, int O,
                           const float* W, const float* g, const float* bch,
                           int catoff)
{
    // knn
    k_sqnorm<<<MROWS/256, 256>>>(Xact, ldx, xoff, C, p.XX);
    if (C >= 16)
        k_dist128<<<dim3(NP/128, NP/128, BQ), 256>>>(Xact, ldx, xoff, p.XX, p.D, C);
    else
        k_dist64<<<dim3(NP/64, NP/64, BQ), 256>>>(Xact, ldx, xoff, p.XX, p.D, C);
    k_topk<<<MROWS/4, 128>>>(p.D, p.IDX);
    // conv
    k_prepw<<<(O*C + 255)/256, 256>>>(W, p.WC, O, C);
    if (C >= 16)
        k_gemm128<<<dim3((2*O)/128, MROWS/128), 256>>>(Xact, ldx, xoff, p.WC, C, p.U, 2*O, 0, C);
    else
        k_gemm64<<<dim3((2*O)/64, MROWS/64), 256>>>(Xact, ldx, xoff, p.WC, C, p.U, 2*O, 0, C);
    // fused gather: stats + hmax/hmin
    k_zero2<<<(O + 255)/256, 256>>>(p.SUM, p.SQ, O);
    k_edge_fuse<<<MROWS/16, 256>>>(p.U, O, p.IDX, p.Y, p.SUM, p.SQ);
    k_bn_finalize<<<(O + 255)/256, 256>>>(p.SUM, p.SQ, g, bch, p.SC, p.SH, O,
                                          1.f/((float)MROWS*(float)KNN));
    k_edge_apply<<<(MROWS*O + 255)/256, 256>>>(p.Y, O, p.SC, p.SH, p.CAT, catoff);
}

extern "C" void kernel_launch(void* const* d_in, const int* in_sizes, int n_in,
                              void* d_out, int out_size)
{
    const float* x   = (const float*)d_in[0];
    const float* W1  = (const float*)d_in[1];
    const float* g1  = (const float*)d_in[2];
    const float* b1  = (const float*)d_in[3];
    const float* W2  = (const float*)d_in[4];
    const float* g2  = (const float*)d_in[5];
    const float* b2  = (const float*)d_in[6];
    const float* W3  = (const float*)d_in[7];
    const float* g3  = (const float*)d_in[8];
    const float* b3  = (const float*)d_in[9];
    const float* W4  = (const float*)d_in[10];
    const float* g4  = (const float*)d_in[11];
    const float* b4  = (const float*)d_in[12];
    const float* W5  = (const float*)d_in[13];
    const float* g5  = (const float*)d_in[14];
    const float* b5  = (const float*)d_in[15];
    const float* Wl1 = (const float*)d_in[16];
    const float* g6  = (const float*)d_in[17];
    const float* b6  = (const float*)d_in[18];
    const float* Wl2 = (const float*)d_in[19];
    const float* bl2 = (const float*)d_in[20];
    const float* g7  = (const float*)d_in[21];
    const float* b7  = (const float*)d_in[22];
    const float* Wl3 = (const float*)d_in[23];
    const float* bl3 = (const float*)d_in[24];
    (void)in_sizes; (void)n_in;

    Ptrs p;
    cudaGetSymbolAddress((void**)&p.XT,   g_XT);
    cudaGetSymbolAddress((void**)&p.CAT,  g_cat);
    cudaGetSymbolAddress((void**)&p.U,    g_U);
    cudaGetSymbolAddress((void**)&p.Y,    g_Y);
    cudaGetSymbolAddress((void**)&p.D,    g_D);
    cudaGetSymbolAddress((void**)&p.XX,   g_xx);
    cudaGetSymbolAddress((void**)&p.WC,   g_Wc);
    cudaGetSymbolAddress((void**)&p.SUM,  g_sum);
    cudaGetSymbolAddress((void**)&p.SQ,   g_sumsq);
    cudaGetSymbolAddress((void**)&p.SC,   g_scale);
    cudaGetSymbolAddress((void**)&p.SH,   g_shift);
    cudaGetSymbolAddress((void**)&p.P,    g_P);
    cudaGetSymbolAddress((void**)&p.H1,   g_h1);
    cudaGetSymbolAddress((void**)&p.H2,   g_h2);
    cudaGetSymbolAddress((void**)&p.IDX,  g_idx);
    cudaGetSymbolAddress((void**)&p.PMAX, g_pmax);
    cudaGetSymbolAddress((void**)&p.PSUM, g_psum);

    // x (8,3,2048) -> row-major (B*N, 3)
    k_transpose_x<<<(BQ*3*NP + 255)/256, 256>>>(x, p.XT);

    run_edge_block(p, p.XT,  3,   0,   3,  64,  W1, g1, b1, 0);
    run_edge_block(p, p.CAT, 512, 0,   64, 64,  W2, g2, b2, 64);
    run_edge_block(p, p.CAT, 512, 64,  64, 128, W3, g3, b3, 128);
    run_edge_block(p, p.CAT, 512, 128, 128, 256, W4, g4, b4, 256);

    // stage 5: Y = cat (16384x512) @ W5^T (1024x512)
    k_gemm128<<<dim3(1024/128, MROWS/128), 256>>>(p.CAT, 512, 0, W5, 512, p.Y, 1024, 0, 512);
    k_zero2<<<(1024 + 255)/256, 256>>>(p.SUM, p.SQ, 1024);
    k_plain_stats<<<dim3(MROWS/256, 4), 256>>>(p.Y, p.SUM, p.SQ);
    k_bn_finalize<<<4, 256>>>(p.SUM, p.SQ, g5, b5, p.SC, p.SH, 1024, 1.f/(float)MROWS);
    k_pool_init<<<(BQ*1024 + 255)/256, 256>>>(p.PMAX, p.PSUM);
    k_pool_part<<<dim3(BQ, 4, NP/256), 256>>>(p.Y, p.SC, p.SH, p.PMAX, p.PSUM);
    k_pool_fin<<<(BQ*1024 + 255)/256, 256>>>(p.PMAX, p.PSUM, p.P);

    // FC head
    k_fc<<<2, 256>>>(p.P,  Wl1, nullptr, p.H1, 512, 2048);
    k_bn_batch<<<2, 256>>>(p.H1, g6, b6, 512);
    k_fc<<<1, 256>>>(p.H1, Wl2, bl2,     p.H2, 256, 512);
    k_bn_batch<<<1, 256>>>(p.H2, g7, b7, 256);
    k_fc<<<1, 64>>>(p.H2, Wl3, bl3, (float*)d_out, 40, 256);
}

// round 3
// speedup vs baseline: 1.2256x; 1.0174x over previous
#include <cuda_runtime.h>
#include <cuda_bf16.h>
#include <float.h>
#include <stdint.h>

#define BQ 8
#define NP 2048
#define KNN 20
#define MROWS (BQ*NP)        // 16384
#define EPSBN 1e-5f
#define CAP 24

// ------------------------- device scratch (global) --------------------------
__device__ float g_XT[MROWS*16];                 // x row-major padded to 16 cols
__device__ float g_cat[(size_t)MROWS*512];
__device__ float g_U[(size_t)MROWS*512];
__device__ float g_Y[(size_t)MROWS*1024];        // stage-5 acts / edge hmax-hmin scratch
__device__ float g_xx[MROWS];
__device__ int   g_idx[MROWS*KNN];
__device__ float g_Wc[512*512];
__device__ float g_sum[1024];
__device__ float g_sumsq[1024];
__device__ float g_scale[1024];
__device__ float g_shift[1024];
__device__ float g_P[BQ*2048];
__device__ float g_h1[BQ*512];
__device__ float g_h2[BQ*256];
__device__ unsigned int g_pmax[BQ*1024];
__device__ float g_psum[BQ*1024];

// ------------------------------ helpers -------------------------------------

__device__ __forceinline__ unsigned int fenc(float v) {
    unsigned int b = __float_as_uint(v);
    return (b & 0x80000000u) ? ~b : (b | 0x80000000u);
}
__device__ __forceinline__ float fdec(unsigned int u) {
    unsigned int b = (u & 0x80000000u) ? (u ^ 0x80000000u) : ~u;
    return __uint_as_float(b);
}

// shared tile store with XOR swizzle:
//   f in [0,512): m=f>>2, kq=f&3; element A[m][4kq+j] -> S[(4kq+j)*128 + (m ^ (kq<<3))]
__device__ __forceinline__ void tile_store(float* S, int f, float4 v)
{
    int m  = f >> 2;
    int kq = f & 3;
    int col = m ^ (kq << 3);
    S[(4*kq + 0)*128 + col] = v.x;
    S[(4*kq + 1)*128 + col] = v.y;
    S[(4*kq + 2)*128 + col] = v.z;
    S[(4*kq + 3)*128 + col] = v.w;
}

// shared layout for fused dist+topk
struct SmT {
    unsigned long long list[128*KNN];   // per-row sorted (desc) top-20 packed keys
    unsigned long long buf[128*CAP];    // per-row candidate buffers
    alignas(16) float As[16*128];
    alignas(16) float Bs[16*128];
    float Dt[128*129];
    int   cnt[128];
    float thr[128];
};

// ------------------------------- kernels ------------------------------------

// x (8,3,2048) -> row-major (B*N, 16) zero-padded
__global__ void k_transpose_pad(const float* __restrict__ x, float* __restrict__ XT)
{
    int i = blockIdx.x * blockDim.x + threadIdx.x;
    if (i >= MROWS) return;
    int b = i >> 11, n = i & (NP-1);
    float v0 = x[(b*3 + 0)*NP + n];
    float v1 = x[(b*3 + 1)*NP + n];
    float v2 = x[(b*3 + 2)*NP + n];
    float4* o = (float4*)(XT + (size_t)i*16);
    o[0] = make_float4(v0, v1, v2, 0.f);
    o[1] = make_float4(0.f, 0.f, 0.f, 0.f);
    o[2] = make_float4(0.f, 0.f, 0.f, 0.f);
    o[3] = make_float4(0.f, 0.f, 0.f, 0.f);
}

__global__ void k_sqnorm(const float* __restrict__ X, int ldx, int xoff, int C,
                         float* __restrict__ xx)
{
    int r = blockIdx.x * blockDim.x + threadIdx.x;
    if (r >= MROWS) return;
    const float* p = X + (size_t)r*ldx + xoff;
    float s = 0.f;
    for (int c = 0; c < C; ++c) { float v = p[c]; s += v*v; }
    xx[r] = s;
}

// ---- fused pairwise-distance GEMM + running top-20 per query row ----
// ranking key: v = 2*dot(x_n,x_m) - xx_m   (xx_n constant per row, dropped)
__global__ void __launch_bounds__(256, 1)
k_dtopk(const float* __restrict__ X, int ldx, int xoff,
        const float* __restrict__ xx, int Kd, int* __restrict__ idxout)
{
    extern __shared__ char smraw[];
    SmT* s = (SmT*)smraw;
    int b  = blockIdx.x;
    int n0 = blockIdx.y * 128;
    size_t base = (size_t)b * NP;
    int t = threadIdx.x, tx = t & 15, ty = t >> 4;

    for (int i = t; i < 128*KNN; i += 256)
        s->list[i] = ((unsigned long long)0x00800000u) << 32;   // (-FLT_MAX, 0)
    if (t < 128) { s->thr[t] = -FLT_MAX; s->cnt[t] = 0; }
    __syncthreads();

    int f0 = t, f1 = t + 256;
    const float* An = X + (base + n0)*(size_t)ldx + xoff;

    for (int m0 = 0; m0 < NP; m0 += 128) {
        const float* Am = X + (base + m0)*(size_t)ldx + xoff;
        float acc[8][8] = {};

        float4 pa0 = *(const float4*)(An + (size_t)(f0>>2)*ldx + (f0&3)*4);
        float4 pa1 = *(const float4*)(An + (size_t)(f1>>2)*ldx + (f1&3)*4);
        float4 pb0 = *(const float4*)(Am + (size_t)(f0>>2)*ldx + (f0&3)*4);
        float4 pb1 = *(const float4*)(Am + (size_t)(f1>>2)*ldx + (f1&3)*4);

        for (int k0 = 0; k0 < Kd; k0 += 16) {
            tile_store(s->As, f0, pa0);
            tile_store(s->As, f1, pa1);
            tile_store(s->Bs, f0, pb0);
            tile_store(s->Bs, f1, pb1);
            __syncthreads();
            if (k0 + 16 < Kd) {
                int kn = k0 + 16;
                pa0 = *(const float4*)(An + (size_t)(f0>>2)*ldx + kn + (f0&3)*4);
                pa1 = *(const float4*)(An + (size_t)(f1>>2)*ldx + kn + (f1&3)*4);
                pb0 = *(const float4*)(Am + (size_t)(f0>>2)*ldx + kn + (f0&3)*4);
                pb1 = *(const float4*)(Am + (size_t)(f1>>2)*ldx + kn + (f1&3)*4);
            }
#pragma unroll
            for (int kk = 0; kk < 16; ++kk) {
                int swz = (kk >> 2) << 3;
                const float4* pa = (const float4*)&s->As[kk*128 + ((ty*8) ^ swz)];
                const float4* pb = (const float4*)&s->Bs[kk*128 + ((tx*8) ^ swz)];
                float4 a03 = pa[0], a47 = pa[1];
                float4 b03 = pb[0], b47 = pb[1];
                float a_[8] = {a03.x,a03.y,a03.z,a03.w,a47.x,a47.y,a47.z,a47.w};
                float b_[8] = {b03.x,b03.y,b03.z,b03.w,b47.x,b47.y,b47.z,b47.w};
#pragma unroll
                for (int i = 0; i < 8; ++i)
#pragma unroll
                    for (int j = 0; j < 8; ++j) acc[i][j] += a_[i]*b_[j];
            }
            __syncthreads();
        }

        // epilogue: value, D tile for overflow rescan, candidate push
        float xm[8];
#pragma unroll
        for (int j = 0; j < 8; ++j) xm[j] = xx[base + m0 + tx*8 + j];
#pragma unroll
        for (int i = 0; i < 8; ++i) {
            int row = ty*8 + i;
            float thr_r = s->thr[row];
#pragma unroll
            for (int j = 0; j < 8; ++j) {
                float v = 2.f*acc[i][j] - xm[j];
                int col = tx*8 + j;
                s->Dt[row*129 + col] = v;
                if (v > thr_r) {
                    int pos = atomicAdd(&s->cnt[row], 1);
                    if (pos < CAP)
                        s->buf[row*CAP + pos] =
                            (((unsigned long long)fenc(v)) << 32) | (unsigned)(m0 + col);
                }
            }
        }
        __syncthreads();

        // merge: thread r owns row r
        if (t < 128) {
            unsigned long long* L = &s->list[t*KNN];
            int c = s->cnt[t];
            if (c > CAP) {
                for (int col = 0; col < 128; ++col) {
                    float v = s->Dt[t*129 + col];
                    unsigned long long key =
                        (((unsigned long long)fenc(v)) << 32) | (unsigned)(m0 + col);
                    if (key > L[KNN-1]) {
                        int q = KNN-1;
                        while (q > 0 && L[q-1] < key) { L[q] = L[q-1]; --q; }
                        L[q] = key;
                    }
                }
            } else {
                for (int qq = 0; qq < c; ++qq) {
                    unsigned long long key = s->buf[t*CAP + qq];
                    if (key > L[KNN-1]) {
                        int q = KNN-1;
                        while (q > 0 && L[q-1] < key) { L[q] = L[q-1]; --q; }
                        L[q] = key;
                    }
                }
            }
            s->thr[t] = fdec((unsigned)(L[KNN-1] >> 32));
            s->cnt[t] = 0;
        }
        __syncthreads();
    }

    if (t < 128) {
        const unsigned long long* L = &s->list[t*KNN];
        int* op = idxout + (base + n0 + t)*KNN;
#pragma unroll
        for (int q = 0; q < KNN; ++q) op[q] = (int)(L[q] & 0xffffffffu);
    }
}

// ---- 128x128x16 fp32 GEMM (plain) ----
__global__ void __launch_bounds__(256, 2)
k_gemm128(const float* __restrict__ A, int lda, int aoff,
          const float* __restrict__ Bw, int ldb,
          float* __restrict__ Cm, int ldc, int coff,
          int Kd)
{
    __shared__ float As[16*128];
    __shared__ float Bs[16*128];
    int n0 = blockIdx.x * 128;
    int m0 = blockIdx.y * 128;
    int t  = threadIdx.x;
    int tx = t & 15, ty = t >> 4;

    float acc[8][8] = {};
    int f0 = t, f1 = t + 256;
    float4 pa0 = *(const float4*)(A  + (size_t)(m0 + (f0>>2))*lda + aoff + (f0&3)*4);
    float4 pa1 = *(const float4*)(A  + (size_t)(m0 + (f1>>2))*lda + aoff + (f1&3)*4);
    float4 pb0 = *(const float4*)(Bw + (size_t)(n0 + (f0>>2))*ldb + (f0&3)*4);
    float4 pb1 = *(const float4*)(Bw + (size_t)(n0 + (f1>>2))*ldb + (f1&3)*4);

    for (int k0 = 0; k0 < Kd; k0 += 16) {
        tile_store(As, f0, pa0);
        tile_store(As, f1, pa1);
        tile_store(Bs, f0, pb0);
        tile_store(Bs, f1, pb1);
        __syncthreads();
        if (k0 + 16 < Kd) {
            int kn = k0 + 16;
            pa0 = *(const float4*)(A  + (size_t)(m0 + (f0>>2))*lda + aoff + kn + (f0&3)*4);
            pa1 = *(const float4*)(A  + (size_t)(m0 + (f1>>2))*lda + aoff + kn + (f1&3)*4);
            pb0 = *(const float4*)(Bw + (size_t)(n0 + (f0>>2))*ldb + kn + (f0&3)*4);
            pb1 = *(const float4*)(Bw + (size_t)(n0 + (f1>>2))*ldb + kn + (f1&3)*4);
        }
#pragma unroll
        for (int kk = 0; kk < 16; ++kk) {
            int swz = (kk >> 2) << 3;
            const float4* pa = (const float4*)&As[kk*128 + ((ty*8) ^ swz)];
            const float4* pb = (const float4*)&Bs[kk*128 + ((tx*8) ^ swz)];
            float4 a03 = pa[0], a47 = pa[1];
            float4 b03 = pb[0], b47 = pb[1];
            float a_[8] = {a03.x,a03.y,a03.z,a03.w,a47.x,a47.y,a47.z,a47.w};
            float b_[8] = {b03.x,b03.y,b03.z,b03.w,b47.x,b47.y,b47.z,b47.w};
#pragma unroll
            for (int i = 0; i < 8; ++i)
#pragma unroll
                for (int j = 0; j < 8; ++j) acc[i][j] += a_[i]*b_[j];
        }
        __syncthreads();
    }
#pragma unroll
    for (int i = 0; i < 8; ++i) {
        float* cp = Cm + (size_t)(m0 + ty*8 + i)*ldc + coff + n0 + tx*8;
        ((float4*)cp)[0] = make_float4(acc[i][0], acc[i][1], acc[i][2], acc[i][3]);
        ((float4*)cp)[1] = make_float4(acc[i][4], acc[i][5], acc[i][6], acc[i][7]);
    }
}

// ---- 128x128x16 fp32 GEMM with fused per-column (channel) sum/sumsq stats ----
__global__ void __launch_bounds__(256, 2)
k_gemm128s(const float* __restrict__ A, int lda,
           const float* __restrict__ Bw, int ldb,
           float* __restrict__ Cm, int ldc,
           int Kd, float* __restrict__ gsum, float* __restrict__ gsq)
{
    __shared__ float As[16*128];
    __shared__ float Bs[16*128];
    int n0 = blockIdx.x * 128;
    int m0 = blockIdx.y * 128;
    int t  = threadIdx.x;
    int tx = t & 15, ty = t >> 4;

    float acc[8][8] = {};
    int f0 = t, f1 = t + 256;
    float4 pa0 = *(const float4*)(A  + (size_t)(m0 + (f0>>2))*lda + (f0&3)*4);
    float4 pa1 = *(const float4*)(A  + (size_t)(m0 + (f1>>2))*lda + (f1&3)*4);
    float4 pb0 = *(const float4*)(Bw + (size_t)(n0 + (f0>>2))*ldb + (f0&3)*4);
    float4 pb1 = *(const float4*)(Bw + (size_t)(n0 + (f1>>2))*ldb + (f1&3)*4);

    for (int k0 = 0; k0 < Kd; k0 += 16) {
        tile_store(As, f0, pa0);
        tile_store(As, f1, pa1);
        tile_store(Bs, f0, pb0);
        tile_store(Bs, f1, pb1);
        __syncthreads();
        if (k0 + 16 < Kd) {
            int kn = k0 + 16;
            pa0 = *(const float4*)(A  + (size_t)(m0 + (f0>>2))*lda + kn + (f0&3)*4);
            pa1 = *(const float4*)(A  + (size_t)(m0 + (f1>>2))*lda + kn + (f1&3)*4);
            pb0 = *(const float4*)(Bw + (size_t)(n0 + (f0>>2))*ldb + kn + (f0&3)*4);
            pb1 = *(const float4*)(Bw + (size_t)(n0 + (f1>>2))*ldb + kn + (f1&3)*4);
        }
#pragma unroll
        for (int kk = 0; kk < 16; ++kk) {
            int swz = (kk >> 2) << 3;
            const float4* pa = (const float4*)&As[kk*128 + ((ty*8) ^ swz)];
            const float4* pb = (const float4*)&Bs[kk*128 + ((tx*8) ^ swz)];
            float4 a03 = pa[0], a47 = pa[1];
            float4 b03 = pb[0], b47 = pb[1];
            float a_[8] = {a03.x,a03.y,a03.z,a03.w,a47.x,a47.y,a47.z,a47.w};
            float b_[8] = {b03.x,b03.y,b03.z,b03.w,b47.x,b47.y,b47.z,b47.w};
#pragma unroll
            for (int i = 0; i < 8; ++i)
#pragma unroll
                for (int j = 0; j < 8; ++j) acc[i][j] += a_[i]*b_[j];
        }
        __syncthreads();
    }
#pragma unroll
    for (int i = 0; i < 8; ++i) {
        float* cp = Cm + (size_t)(m0 + ty*8 + i)*ldc + n0 + tx*8;
        ((float4*)cp)[0] = make_float4(acc[i][0], acc[i][1], acc[i][2], acc[i][3]);
        ((float4*)cp)[1] = make_float4(acc[i][4], acc[i][5], acc[i][6], acc[i][7]);
    }
    // block-level per-column sums, then one atomic per column
#pragma unroll
    for (int j = 0; j < 8; ++j) {
        float s0 = 0.f, s1 = 0.f;
#pragma unroll
        for (int i = 0; i < 8; ++i) { float v = acc[i][j]; s0 += v; s1 += v*v; }
        As[ty*128 + tx*8 + j] = s0;
        Bs[ty*128 + tx*8 + j] = s1;
    }
    __syncthreads();
    if (t < 128) {
        float a = 0.f, c2 = 0.f;
#pragma unroll
        for (int g = 0; g < 16; ++g) { a += As[g*128 + t]; c2 += Bs[g*128 + t]; }
        atomicAdd(&gsum[n0 + t], a);
        atomicAdd(&gsq [n0 + t], c2);
    }
}

// Wc[o][c] = W[o][c];  Wc[O+o][c] = W[o][Creal+c] - W[o][c], zero-padded to Cpad
__global__ void k_prepw(const float* __restrict__ W, float* __restrict__ Wc,
                        int O, int Creal, int Cpad)
{
    int i = blockIdx.x * blockDim.x + threadIdx.x;
    if (i >= O*Cpad) return;
    int o = i / Cpad, c = i % Cpad;
    float w1 = 0.f, w2 = 0.f;
    if (c < Creal) {
        w1 = W[o*2*Creal + c];
        w2 = W[o*2*Creal + Creal + c];
    }
    Wc[o*Cpad + c]       = w1;
    Wc[(O + o)*Cpad + c] = w2 - w1;
}

__global__ void k_zero2(float* a, float* b, int n)
{
    int i = blockIdx.x * blockDim.x + threadIdx.x;
    if (i < n) { a[i] = 0.f; b[i] = 0.f; }
}

// fused edge gather: BN stats AND per-(row,o) hmax/hmin
__global__ void k_edge_fuse(const float* __restrict__ U, int O,
                            const int* __restrict__ idx,
                            float* __restrict__ HM,
                            float* __restrict__ gsum, float* __restrict__ gsq)
{
    const int ld = 2*O;
    int nsub = 256 / O;
    int o   = threadIdx.x % O;
    int sub = threadIdx.x / O;
    int row0 = blockIdx.x * 16;
    float s0 = 0.f, s1 = 0.f;
    for (int r = row0 + sub; r < row0 + 16; r += nsub) {
        int b = r >> 11;
        float tc = U[(size_t)r*ld + O + o];
        const int* ir = idx + r*KNN;
        float mx = -FLT_MAX, mn = FLT_MAX;
#pragma unroll
        for (int k = 0; k < KNN; ++k) {
            int nb = ir[k];
            float h = U[((size_t)(b << 11) + nb)*ld + o] + tc;
            s0 += h; s1 += h*h;
            mx = fmaxf(mx, h);
            mn = fminf(mn, h);
        }
        HM[(size_t)r*1024 + o]       = mx;
        HM[(size_t)r*1024 + 512 + o] = mn;
    }
    atomicAdd(&gsum[o], s0);
    atomicAdd(&gsq[o],  s1);
}

__global__ void k_bn_finalize(const float* __restrict__ gsum, const float* __restrict__ gsq,
                              const float* __restrict__ g, const float* __restrict__ bch,
                              float* __restrict__ scale, float* __restrict__ shift,
                              int O, float invcnt)
{
    int o = blockIdx.x * blockDim.x + threadIdx.x;
    if (o >= O) return;
    float m  = gsum[o] * invcnt;
    float vv = gsq[o] * invcnt - m*m;
    float sc = g[o] / sqrtf(vv + EPSBN);
    scale[o] = sc;
    shift[o] = bch[o] - m*sc;
}

__global__ void k_edge_apply(const float* __restrict__ HM, int O,
                             const float* __restrict__ scale, const float* __restrict__ shift,
                             float* __restrict__ cat, int catoff)
{
    int i = blockIdx.x * blockDim.x + threadIdx.x;
    if (i >= MROWS*O) return;
    int r = i / O, o = i % O;
    float sc = scale[o], sh = shift[o];
    float h = (sc >= 0.f) ? HM[(size_t)r*1024 + o] : HM[(size_t)r*1024 + 512 + o];
    float z = h*sc + sh;
    cat[(size_t)r*512 + catoff + o] = (z >= 0.f) ? z : 0.2f*z;
}

__global__ void k_pool_init(unsigned int* pmax, float* psum)
{
    int i = blockIdx.x * blockDim.x + threadIdx.x;
    if (i < BQ*1024) { pmax[i] = 0u; psum[i] = 0.f; }
}

__global__ void k_pool_part(const float* __restrict__ Y,
                            const float* __restrict__ scale, const float* __restrict__ shift,
                            unsigned int* __restrict__ pmax, float* __restrict__ psum)
{
    int b  = blockIdx.x;
    int o  = blockIdx.y * 256 + threadIdx.x;
    int n0 = blockIdx.z * 256;
    float sc = scale[o], sh = shift[o];
    float mx = -FLT_MAX, sm = 0.f;
    for (int n = n0; n < n0 + 256; ++n) {
        float v = Y[((size_t)b*NP + n)*1024 + o]*sc + sh;
        v = (v >= 0.f) ? v : 0.2f*v;
        mx = fmaxf(mx, v);
        sm += v;
    }
    atomicMax(&pmax[b*1024 + o], fenc(mx));
    atomicAdd(&psum[b*1024 + o], sm);
}

__global__ void k_pool_fin(const unsigned int* __restrict__ pmax,
                           const float* __restrict__ psum, float* __restrict__ P)
{
    int i = blockIdx.x * blockDim.x + threadIdx.x;
    if (i >= BQ*1024) return;
    int b = i >> 10, o = i & 1023;
    P[b*2048 + o]        = fdec(pmax[i]);
    P[b*2048 + 1024 + o] = psum[i] * (1.f/(float)NP);
}

__global__ void k_fc(const float* __restrict__ In, const float* __restrict__ W,
                     const float* __restrict__ bias, float* __restrict__ Out,
                     int F, int Kd)
{
    int f = blockIdx.x * blockDim.x + threadIdx.x;
    if (f >= F) return;
    float acc[BQ] = {};
    const float* wr = W + (size_t)f*Kd;
    for (int j = 0; j < Kd; ++j) {
        float w = wr[j];
#pragma unroll
        for (int b = 0; b < BQ; ++b) acc[b] += In[b*Kd + j]*w;
    }
    float bb = bias ? bias[f] : 0.f;
#pragma unroll
    for (int b = 0; b < BQ; ++b) Out[b*F + f] = acc[b] + bb;
}

__global__ void k_bn_batch(float* __restrict__ X, const float* __restrict__ g,
                           const float* __restrict__ bch, int F)
{
    int f = blockIdx.x * blockDim.x + threadIdx.x;
    if (f >= F) return;
    float m = 0.f;
#pragma unroll
    for (int b = 0; b < BQ; ++b) m += X[b*F + f];
    m *= (1.f/BQ);
    float vv = 0.f;
#pragma unroll
    for (int b = 0; b < BQ; ++b) { float d = X[b*F + f] - m; vv += d*d; }
    vv *= (1.f/BQ);
    float sc = g[f] / sqrtf(vv + EPSBN);
    float sh = bch[f] - m*sc;
#pragma unroll
    for (int b = 0; b < BQ; ++b) {
        float z = X[b*F + f]*sc + sh;
        X[b*F + f] = (z >= 0.f) ? z : 0.2f*z;
    }
}

// ------------------------------- host side ----------------------------------

struct Ptrs {
    float *XT, *CAT, *U, *Y, *XX, *WC, *SUM, *SQ, *SC, *SH, *P, *H1, *H2, *PSUM;
    unsigned int *PMAX;
    int *IDX;
};

static void run_edge_block(const Ptrs& p,
                           const float* Xact, int ldx, int xoff, int Creal, int Cpad,
                           int O, const float* W, const float* g, const float* bch,
                           int catoff)
{
    k_sqnorm<<<MROWS/256, 256>>>(Xact, ldx, xoff, Creal, p.XX);
    k_dtopk<<<dim3(BQ, NP/128), 256, (int)sizeof(SmT)>>>(Xact, ldx, xoff, p.XX, Cpad, p.IDX);
    k_prepw<<<(O*Cpad + 255)/256, 256>>>(W, p.WC, O, Creal, Cpad);
    k_gemm128<<<dim3((2*O)/128, MROWS/128), 256>>>(Xact, ldx, xoff, p.WC, Cpad, p.U, 2*O, 0, Cpad);
    k_zero2<<<(O + 255)/256, 256>>>(p.SUM, p.SQ, O);
    k_edge_fuse<<<MROWS/16, 256>>>(p.U, O, p.IDX, p.Y, p.SUM, p.SQ);
    k_bn_finalize<<<(O + 255)/256, 256>>>(p.SUM, p.SQ, g, bch, p.SC, p.SH, O,
                                          1.f/((float)MROWS*(float)KNN));
    k_edge_apply<<<(MROWS*O + 255)/256, 256>>>(p.Y, O, p.SC, p.SH, p.CAT, catoff);
}

extern "C" void kernel_launch(void* const* d_in, const int* in_sizes, int n_in,
                              void* d_out, int out_size)
{
    const float* x   = (const float*)d_in[0];
    const float* W1  = (const float*)d_in[1];
    const float* g1  = (const float*)d_in[2];
    const float* b1  = (const float*)d_in[3];
    const float* W2  = (const float*)d_in[4];
    const float* g2  = (const float*)d_in[5];
    const float* b2  = (const float*)d_in[6];
    const float* W3  = (const float*)d_in[7];
    const float* g3  = (const float*)d_in[8];
    const float* b3  = (const float*)d_in[9];
    const float* W4  = (const float*)d_in[10];
    const float* g4  = (const float*)d_in[11];
    const float* b4  = (const float*)d_in[12];
    const float* W5  = (const float*)d_in[13];
    const float* g5  = (const float*)d_in[14];
    const float* b5  = (const float*)d_in[15];
    const float* Wl1 = (const float*)d_in[16];
    const float* g6  = (const float*)d_in[17];
    const float* b6  = (const float*)d_in[18];
    const float* Wl2 = (const float*)d_in[19];
    const float* bl2 = (const float*)d_in[20];
    const float* g7  = (const float*)d_in[21];
    const float* b7  = (const float*)d_in[22];
    const float* Wl3 = (const float*)d_in[23];
    const float* bl3 = (const float*)d_in[24];
    (void)in_sizes; (void)n_in;

    Ptrs p;
    cudaGetSymbolAddress((void**)&p.XT,   g_XT);
    cudaGetSymbolAddress((void**)&p.CAT,  g_cat);
    cudaGetSymbolAddress((void**)&p.U,    g_U);
    cudaGetSymbolAddress((void**)&p.Y,    g_Y);
    cudaGetSymbolAddress((void**)&p.XX,   g_xx);
    cudaGetSymbolAddress((void**)&p.WC,   g_Wc);
    cudaGetSymbolAddress((void**)&p.SUM,  g_sum);
    cudaGetSymbolAddress((void**)&p.SQ,   g_sumsq);
    cudaGetSymbolAddress((void**)&p.SC,   g_scale);
    cudaGetSymbolAddress((void**)&p.SH,   g_shift);
    cudaGetSymbolAddress((void**)&p.P,    g_P);
    cudaGetSymbolAddress((void**)&p.H1,   g_h1);
    cudaGetSymbolAddress((void**)&p.H2,   g_h2);
    cudaGetSymbolAddress((void**)&p.IDX,  g_idx);
    cudaGetSymbolAddress((void**)&p.PMAX, g_pmax);
    cudaGetSymbolAddress((void**)&p.PSUM, g_psum);

    cudaFuncSetAttribute(k_dtopk, cudaFuncAttributeMaxDynamicSharedMemorySize,
                         (int)sizeof(SmT));

    k_transpose_pad<<<MROWS/256, 256>>>(x, p.XT);

    run_edge_block(p, p.XT,  16,  0,   3,   16,  64,  W1, g1, b1, 0);
    run_edge_block(p, p.CAT, 512, 0,   64,  64,  64,  W2, g2, b2, 64);
    run_edge_block(p, p.CAT, 512, 64,  64,  64,  128, W3, g3, b3, 128);
    run_edge_block(p, p.CAT, 512, 128, 128, 128, 256, W4, g4, b4, 256);

    // stage 5: Y = cat (16384x512) @ W5^T (1024x512), fused BN stats
    k_zero2<<<(1024 + 255)/256, 256>>>(p.SUM, p.SQ, 1024);
    k_gemm128s<<<dim3(1024/128, MROWS/128), 256>>>(p.CAT, 512, W5, 512, p.Y, 1024,
                                                   512, p.SUM, p.SQ);
    k_bn_finalize<<<4, 256>>>(p.SUM, p.SQ, g5, b5, p.SC, p.SH, 1024, 1.f/(float)MROWS);
    k_pool_init<<<(BQ*1024 + 255)/256, 256>>>(p.PMAX, p.PSUM);
    k_pool_part<<<dim3(BQ, 4, NP/256), 256>>>(p.Y, p.SC, p.SH, p.PMAX, p.PSUM);
    k_pool_fin<<<(BQ*1024 + 255)/256, 256>>>(p.PMAX, p.PSUM, p.P);

    // FC head
    k_fc<<<2, 256>>>(p.P,  Wl1, nullptr, p.H1, 512, 2048);
    k_bn_batch<<<2, 256>>>(p.H1, g6, b6, 512);
    k_fc<<<1, 256>>>(p.H1, Wl2, bl2,     p.H2, 256, 512);
    k_bn_batch<<<1, 256>>>(p.H2, g7, b7, 256);
    k_fc<<<1, 64>>>(p.H2, Wl3, bl3, (float*)d_out, 40, 256);
}